// round 4
// baseline (speedup 1.0000x reference)
#include <cuda_runtime.h>
#include <math.h>
#include <stdint.h>

#define N_NODES 10000
#define N_EDGES 80000
#define IN_DIM  1024
#define HID     4096
#define OUT_DIM 256

// ---------------------------------------------------------------------------
// Scratch (device globals)
// ---------------------------------------------------------------------------
__device__ __align__(16) float g_agg1[(size_t)N_NODES * IN_DIM];   // 40 MB
__device__ __align__(16) float g_h[(size_t)N_NODES * HID];         // 160 MB
__device__ __align__(16) float g_t2[(size_t)N_NODES * OUT_DIM];    // 10 MB
__device__ __align__(16) float g_aggo[(size_t)N_NODES * OUT_DIM];  // 10 MB
__device__ __align__(16) float g_cnt[N_NODES];
__device__ __align__(16) float g_xc[(size_t)N_NODES * IN_DIM];     // 40 MB
__device__ __align__(16) float g_w1lc[(size_t)HID * IN_DIM];       // 16 MB
__device__ __align__(16) float g_w1rc[(size_t)HID * IN_DIM];       // 16 MB
__device__ __align__(16) float g_w2lc[(size_t)OUT_DIM * HID];      // 4 MB
__device__ __align__(16) float g_w2rc[(size_t)OUT_DIM * HID];      // 4 MB

// ---------------------------------------------------------------------------
// Helpers
// ---------------------------------------------------------------------------
__device__ __forceinline__ float tf32r(float x) {
    uint32_t u; asm("cvt.rna.tf32.f32 %0, %1;" : "=r"(u) : "f"(x));
    return __uint_as_float(u);
}
__device__ __forceinline__ void mma_tf32(float c[4],
        uint32_t a0, uint32_t a1, uint32_t a2, uint32_t a3,
        uint32_t b0, uint32_t b1) {
    asm volatile(
        "mma.sync.aligned.m16n8k8.row.col.f32.tf32.tf32.f32 "
        "{%0,%1,%2,%3},{%4,%5,%6,%7},{%8,%9},{%0,%1,%2,%3};"
        : "+f"(c[0]), "+f"(c[1]), "+f"(c[2]), "+f"(c[3])
        : "r"(a0), "r"(a1), "r"(a2), "r"(a3), "r"(b0), "r"(b1));
}
__device__ __forceinline__ void cp_async16(uint32_t smem, const void* g, bool valid) {
    int sz = valid ? 16 : 0;
    asm volatile("cp.async.ca.shared.global [%0], [%1], 16, %2;\n"
                 :: "r"(smem), "l"(g), "r"(sz));
}
__device__ __forceinline__ void cp_commit() { asm volatile("cp.async.commit_group;\n"); }
template<int W> __device__ __forceinline__ void cp_wait() {
    asm volatile("cp.async.wait_group %0;\n" :: "n"(W));
}

// ---------------------------------------------------------------------------
// TF32 tensor-core GEMM:  C[M,N] = A[M,K] @ W[N,K]^T
// BM=BN=128, BK=16, 256 threads = 8 warps (2m x 4n), warp tile 64x32,
// mma.sync.m16n8k8.tf32, 3-stage cp.async pipeline.
// Operands MUST be tf32-pre-rounded in gmem (no in-loop cvt).
//
// NPAIRS==2: C0 = act(A0@W0^T + A1@W1^T + bias)           (layer 1 fusion)
// SPLITN   : grid.x doubled: first half -> C0 = A0@W0^T + bias
//                            second half -> C1 = A0@W1^T  (no bias)
// RELU     : also tf32-round the stored result (feeds next GEMM)
// ---------------------------------------------------------------------------
#define BM 128
#define BN 128
#define BK 16
#define SKEW 20
#define NSTAGE 3

__device__ __forceinline__ void load_tile(float (*sA)[SKEW], float (*sB)[SKEW],
        const float* __restrict__ A, const float* __restrict__ W,
        int M, int K, int row0, int col0, int k0, int tid) {
#pragma unroll
    for (int it = 0; it < 2; it++) {
        int i  = tid + it * 256;
        int r  = i >> 2;
        int k4 = (i & 3) * 4;
        bool okA = (row0 + r) < M;
        int ra = okA ? (row0 + r) : 0;
        uint32_t sa = (uint32_t)__cvta_generic_to_shared(&sA[r][k4]);
        cp_async16(sa, A + (size_t)ra * K + k0 + k4, okA);
        uint32_t sb = (uint32_t)__cvta_generic_to_shared(&sB[r][k4]);
        cp_async16(sb, W + (size_t)(col0 + r) * K + k0 + k4, true);
    }
    cp_commit();
}

template<int NPAIRS, bool SPLITN, bool RELU>
__global__ __launch_bounds__(256, 2)
void gemm_tf32_kernel(const float* __restrict__ A0, const float* __restrict__ W0,
                      const float* __restrict__ A1, const float* __restrict__ W1,
                      float* __restrict__ C0, float* __restrict__ C1,
                      const float* __restrict__ bias,
                      int M, int N, int K) {
    __shared__ float sA[NSTAGE][BM][SKEW];
    __shared__ float sB[NSTAGE][BN][SKEW];

    const int tid = threadIdx.x;
    const int bx = blockIdx.x, by = blockIdx.y;

    const float* A = A0;
    const float* W = W0;
    float*       C = C0;
    bool useBias = (bias != nullptr);
    int col0;
    if (SPLITN) {
        int nHalf = (N / BN);
        bool sel = bx >= nHalf;
        col0 = (sel ? bx - nHalf : bx) * BN;
        if (sel) { W = W1; C = C1; useBias = false; }
    } else {
        col0 = bx * BN;
    }
    const int row0 = by * BM;

    const int w  = tid >> 5, lane = tid & 31;
    const int wr = w >> 2;
    const int wc = w & 3;
    const int g  = lane >> 2;
    const int tg = lane & 3;

    float acc[4][4][4];
#pragma unroll
    for (int mi = 0; mi < 4; mi++)
#pragma unroll
        for (int ni = 0; ni < 4; ni++)
#pragma unroll
            for (int q = 0; q < 4; q++) acc[mi][ni][q] = 0.f;

    const int stepsPerK = K / BK;
    const int nSteps = stepsPerK * NPAIRS;

    auto src_of = [&](int s, const float*& Ap, const float*& Wp, int& k0) {
        if (NPAIRS == 2 && s >= stepsPerK) { Ap = A1; Wp = W1; k0 = (s - stepsPerK) * BK; }
        else { Ap = A; Wp = W; k0 = s * BK; }
    };

    // prologue: fill NSTAGE-1 stages
#pragma unroll
    for (int s = 0; s < NSTAGE - 1; s++) {
        const float *Ap, *Wp; int k0;
        src_of(s, Ap, Wp, k0);
        load_tile(sA[s], sB[s], Ap, Wp, M, K, row0, col0, k0, tid);
    }

    for (int t = 0; t < nSteps; t++) {
        const int buf = t % NSTAGE;
        // issue load for t + NSTAGE - 1
        if (t + NSTAGE - 1 < nSteps) {
            const float *Ap, *Wp; int k0;
            src_of(t + NSTAGE - 1, Ap, Wp, k0);
            load_tile(sA[(t + NSTAGE - 1) % NSTAGE], sB[(t + NSTAGE - 1) % NSTAGE],
                      Ap, Wp, M, K, row0, col0, k0, tid);
            cp_wait<NSTAGE - 1>();
        } else {
            cp_wait<0>();
        }
        __syncthreads();

#pragma unroll
        for (int ks = 0; ks < BK; ks += 8) {
            uint32_t af[4][4], bf[4][2];
#pragma unroll
            for (int mi = 0; mi < 4; mi++) {
                int m = wr * 64 + mi * 16;
                af[mi][0] = __float_as_uint(sA[buf][m + g    ][ks + tg]);
                af[mi][1] = __float_as_uint(sA[buf][m + g + 8][ks + tg]);
                af[mi][2] = __float_as_uint(sA[buf][m + g    ][ks + tg + 4]);
                af[mi][3] = __float_as_uint(sA[buf][m + g + 8][ks + tg + 4]);
            }
#pragma unroll
            for (int ni = 0; ni < 4; ni++) {
                int n = wc * 32 + ni * 8;
                bf[ni][0] = __float_as_uint(sB[buf][n + g][ks + tg]);
                bf[ni][1] = __float_as_uint(sB[buf][n + g][ks + tg + 4]);
            }
#pragma unroll
            for (int mi = 0; mi < 4; mi++)
#pragma unroll
                for (int ni = 0; ni < 4; ni++)
                    mma_tf32(acc[mi][ni], af[mi][0], af[mi][1], af[mi][2], af[mi][3],
                             bf[ni][0], bf[ni][1]);
        }
        __syncthreads();
    }

    // epilogue
#pragma unroll
    for (int mi = 0; mi < 4; mi++) {
        int rbase = row0 + wr * 64 + mi * 16 + g;
#pragma unroll
        for (int half = 0; half < 2; half++) {
            int r = rbase + half * 8;
            if (r < M) {
                float* crow = C + (size_t)r * N;
#pragma unroll
                for (int ni = 0; ni < 4; ni++) {
                    int c = col0 + wc * 32 + ni * 8 + 2 * tg;
                    float v0 = acc[mi][ni][half * 2 + 0];
                    float v1 = acc[mi][ni][half * 2 + 1];
                    if (useBias) { v0 += bias[c]; v1 += bias[c + 1]; }
                    if (RELU) {
                        v0 = tf32r(fmaxf(v0, 0.f));   // feeds next GEMM: pre-round
                        v1 = tf32r(fmaxf(v1, 0.f));
                    }
                    *(float2*)(crow + c) = make_float2(v0, v1);
                }
            }
        }
    }
}

// ---------------------------------------------------------------------------
// Utility kernels
// ---------------------------------------------------------------------------
__global__ void zero_kernel(float* __restrict__ p, size_t n4) {
    size_t i = (size_t)blockIdx.x * blockDim.x + threadIdx.x;
    size_t stride = (size_t)gridDim.x * blockDim.x;
    float4 z = make_float4(0.f, 0.f, 0.f, 0.f);
    float4* p4 = (float4*)p;
    for (; i < n4; i += stride) p4[i] = z;
}

__global__ void cvt_tf32_kernel(const float* __restrict__ s, float* __restrict__ d, size_t n4) {
    size_t i = (size_t)blockIdx.x * blockDim.x + threadIdx.x;
    size_t stride = (size_t)gridDim.x * blockDim.x;
    const float4* s4 = (const float4*)s;
    float4* d4 = (float4*)d;
    for (; i < n4; i += stride) {
        float4 v = s4[i];
        v.x = tf32r(v.x); v.y = tf32r(v.y); v.z = tf32r(v.z); v.w = tf32r(v.w);
        d4[i] = v;
    }
}

__global__ void count_kernel(const int* __restrict__ dst, float* __restrict__ cnt) {
    int e = blockIdx.x * blockDim.x + threadIdx.x;
    if (e < N_EDGES) atomicAdd(&cnt[dst[e]], 1.0f);
}

__global__ void scatter_kernel(const float* __restrict__ X,
                               const int* __restrict__ src,
                               const int* __restrict__ dst,
                               float* __restrict__ agg, int D4) {
    int e = blockIdx.x;
    int s = src[e], d = dst[e];
    const float4* xs = (const float4*)(X + (size_t)s * D4 * 4);
    float* ag = agg + (size_t)d * D4 * 4;
    for (int i = threadIdx.x; i < D4; i += blockDim.x) {
        float4 v = xs[i];
        atomicAdd(ag + 4 * i + 0, v.x);
        atomicAdd(ag + 4 * i + 1, v.y);
        atomicAdd(ag + 4 * i + 2, v.z);
        atomicAdd(ag + 4 * i + 3, v.w);
    }
}

// mean + tf32 rounding (output feeds the tf32 GEMM)
__global__ void mean_kernel(float* __restrict__ agg, const float* __restrict__ cnt, int D4) {
    int n = blockIdx.x;
    float inv = 1.0f / fmaxf(cnt[n], 1.0f);
    float4* p = (float4*)(agg + (size_t)n * D4 * 4);
    for (int i = threadIdx.x; i < D4; i += blockDim.x) {
        float4 v = p[i];
        v.x = tf32r(v.x * inv); v.y = tf32r(v.y * inv);
        v.z = tf32r(v.z * inv); v.w = tf32r(v.w * inv);
        p[i] = v;
    }
}

__global__ void final_kernel(float* __restrict__ out,
                             const float* __restrict__ aggo,
                             const float* __restrict__ cnt) {
    __shared__ float red[256];
    const int n = blockIdx.x;
    const int t = threadIdx.x;
    float inv = 1.0f / fmaxf(cnt[n], 1.0f);
    size_t idx = (size_t)n * OUT_DIM + t;
    float v = out[idx] + aggo[idx] * inv;

    red[t] = v;
    __syncthreads();
    for (int s = 128; s > 0; s >>= 1) {
        if (t < s) red[t] = fmaxf(red[t], red[t + s]);
        __syncthreads();
    }
    float m = red[0];
    __syncthreads();

    red[t] = expf(v - m);
    __syncthreads();
    for (int s = 128; s > 0; s >>= 1) {
        if (t < s) red[t] += red[t + s];
        __syncthreads();
    }
    float lse = logf(red[0]);
    out[idx] = v - m - lse;
}

// ---------------------------------------------------------------------------
// Launch
// ---------------------------------------------------------------------------
extern "C" void kernel_launch(void* const* d_in, const int* in_sizes, int n_in,
                              void* d_out, int out_size) {
    const float* x   = (const float*)d_in[0];
    const int*   ei  = (const int*)  d_in[1];
    const float* W1l = (const float*)d_in[2];
    const float* b1l = (const float*)d_in[3];
    const float* W1r = (const float*)d_in[4];
    const float* W2l = (const float*)d_in[5];
    const float* b2l = (const float*)d_in[6];
    const float* W2r = (const float*)d_in[7];
    float* out = (float*)d_out;

    const int* src = ei;
    const int* dst = ei + N_EDGES;

    float *agg1, *h, *t2, *aggo, *cnt, *xc, *w1lc, *w1rc, *w2lc, *w2rc;
    cudaGetSymbolAddress((void**)&agg1, g_agg1);
    cudaGetSymbolAddress((void**)&h,    g_h);
    cudaGetSymbolAddress((void**)&t2,   g_t2);
    cudaGetSymbolAddress((void**)&aggo, g_aggo);
    cudaGetSymbolAddress((void**)&cnt,  g_cnt);
    cudaGetSymbolAddress((void**)&xc,   g_xc);
    cudaGetSymbolAddress((void**)&w1lc, g_w1lc);
    cudaGetSymbolAddress((void**)&w1rc, g_w1rc);
    cudaGetSymbolAddress((void**)&w2lc, g_w2lc);
    cudaGetSymbolAddress((void**)&w2rc, g_w2rc);

    // ---- counts + layer-1 aggregation ----
    zero_kernel<<<2048, 256>>>(agg1, (size_t)N_NODES * IN_DIM / 4);
    zero_kernel<<<512, 256>>>(aggo, (size_t)N_NODES * OUT_DIM / 4);
    zero_kernel<<<16, 256>>>(cnt, N_NODES / 4);
    count_kernel<<<(N_EDGES + 255) / 256, 256>>>(dst, cnt);
    scatter_kernel<<<N_EDGES, 256>>>(x, src, dst, agg1, IN_DIM / 4);
    mean_kernel<<<N_NODES, 256>>>(agg1, cnt, IN_DIM / 4);

    // ---- tf32 pre-rounding of MMA operands (once; inner loop loads raw bits) ----
    cvt_tf32_kernel<<<2048, 256>>>(x,   xc,   (size_t)N_NODES * IN_DIM / 4);
    cvt_tf32_kernel<<<1024, 256>>>(W1l, w1lc, (size_t)HID * IN_DIM / 4);
    cvt_tf32_kernel<<<1024, 256>>>(W1r, w1rc, (size_t)HID * IN_DIM / 4);
    cvt_tf32_kernel<<<256, 256>>>(W2l, w2lc, (size_t)OUT_DIM * HID / 4);
    cvt_tf32_kernel<<<256, 256>>>(W2r, w2rc, (size_t)OUT_DIM * HID / 4);

    // ---- layer 1: h = relu(mean1@W1l^T + x@W1r^T + b1) (fused dual-K GEMM) ----
    {
        dim3 grid(HID / BN, (N_NODES + BM - 1) / BM);
        gemm_tf32_kernel<2, false, true><<<grid, 256>>>(
            agg1, w1lc, xc, w1rc, h, nullptr, b1l, N_NODES, HID, IN_DIM);
    }

    // ---- layer 2: out = h@W2r^T + b2 ; t2 = h@W2l^T (fused split-N GEMM) ----
    {
        dim3 grid(2 * OUT_DIM / BN, (N_NODES + BM - 1) / BM);
        gemm_tf32_kernel<1, true, false><<<grid, 256>>>(
            h, w2rc, nullptr, w2lc, out, t2, b2l, N_NODES, OUT_DIM, HID);
    }

    // ---- scatter-mean of t2 in 256-dim space ----
    scatter_kernel<<<N_EDGES, 64>>>(t2, src, dst, aggo, OUT_DIM / 4);

    // ---- out = log_softmax(out + aggo/cnt) ----
    final_kernel<<<N_NODES, 256>>>(out, aggo, cnt);
}

// round 5
// speedup vs baseline: 1.8419x; 1.8419x over previous
#include <cuda_runtime.h>
#include <cuda_bf16.h>
#include <math.h>
#include <stdint.h>

#define N_NODES 10000
#define N_EDGES 80000
#define IN_DIM  1024
#define HID     4096
#define OUT_DIM 256

// ---------------------------------------------------------------------------
// Scratch (device globals)
// ---------------------------------------------------------------------------
__device__ __align__(16) float g_agg1[(size_t)N_NODES * IN_DIM];            // 40 MB fp32 (atomics)
__device__ __align__(16) __nv_bfloat16 g_agg1b[(size_t)N_NODES * IN_DIM];   // 20 MB
__device__ __align__(16) __nv_bfloat16 g_xb[(size_t)N_NODES * IN_DIM];      // 20 MB
__device__ __align__(16) __nv_bfloat16 g_h[(size_t)N_NODES * HID];          // 80 MB
__device__ __align__(16) float g_t2[(size_t)N_NODES * OUT_DIM];             // 10 MB
__device__ __align__(16) float g_aggo[(size_t)N_NODES * OUT_DIM];           // 10 MB
__device__ __align__(16) float g_cnt[N_NODES];
__device__ __align__(16) __nv_bfloat16 g_w1lb[(size_t)HID * IN_DIM];        // 8 MB
__device__ __align__(16) __nv_bfloat16 g_w1rb[(size_t)HID * IN_DIM];        // 8 MB
__device__ __align__(16) __nv_bfloat16 g_w2lb[(size_t)OUT_DIM * HID];       // 2 MB
__device__ __align__(16) __nv_bfloat16 g_w2rb[(size_t)OUT_DIM * HID];       // 2 MB

// ---------------------------------------------------------------------------
// Helpers
// ---------------------------------------------------------------------------
__device__ __forceinline__ void mma_bf16(float c[4],
        uint32_t a0, uint32_t a1, uint32_t a2, uint32_t a3,
        uint32_t b0, uint32_t b1) {
    asm volatile(
        "mma.sync.aligned.m16n8k16.row.col.f32.bf16.bf16.f32 "
        "{%0,%1,%2,%3},{%4,%5,%6,%7},{%8,%9},{%0,%1,%2,%3};"
        : "+f"(c[0]), "+f"(c[1]), "+f"(c[2]), "+f"(c[3])
        : "r"(a0), "r"(a1), "r"(a2), "r"(a3), "r"(b0), "r"(b1));
}
__device__ __forceinline__ void ldsm_x4(uint32_t r[4], uint32_t addr) {
    asm volatile("ldmatrix.sync.aligned.m8n8.x4.shared.b16 {%0,%1,%2,%3}, [%4];"
                 : "=r"(r[0]), "=r"(r[1]), "=r"(r[2]), "=r"(r[3]) : "r"(addr));
}
__device__ __forceinline__ void cp_async16(uint32_t smem, const void* g, bool valid) {
    int sz = valid ? 16 : 0;
    asm volatile("cp.async.ca.shared.global [%0], [%1], 16, %2;\n"
                 :: "r"(smem), "l"(g), "r"(sz));
}
__device__ __forceinline__ void cp_commit() { asm volatile("cp.async.commit_group;\n"); }
template<int W> __device__ __forceinline__ void cp_wait() {
    asm volatile("cp.async.wait_group %0;\n" :: "n"(W));
}

// ---------------------------------------------------------------------------
// BF16 tensor-core GEMM:  C[M,N] = A[M,K] @ W[N,K]^T   (A,W bf16; C fp32/bf16)
// BM=BN=128, BK=32 (bf16), 256 threads = 8 warps (2m x 4n), warp tile 64x32,
// mma.sync.m16n8k16 + ldmatrix.x4, double-buffered cp.async.
// smem rows padded to 40 bf16 (80 B): conflict-free ldmatrix, 16B-aligned cp.async.
//
// NPAIRS==2: C0 = relu(A0@W0^T + A1@W1^T + bias), stored bf16   (layer 1)
// SPLITN   : grid.x doubled: first half -> C0(fp32) = A0@W0^T + bias
//                            second half -> C1(fp32) = A0@W1^T  (layer 2)
// ---------------------------------------------------------------------------
#define BM 128
#define BN 128
#define BK 32
#define ROWB 80            // bytes per padded smem row (32*2 + 16)
#define STAGE (128 * ROWB) // 10240 B per tile

__device__ __forceinline__ void load_tile(char* sA, char* sB,
        const __nv_bfloat16* __restrict__ A, const __nv_bfloat16* __restrict__ W,
        int M, int K, int row0, int col0, int k0, int tid) {
#pragma unroll
    for (int it = 0; it < 2; it++) {
        int c = tid + it * 256;         // 0..511
        int r = c >> 2, q = c & 3;      // row, 16B chunk
        bool okA = (row0 + r) < M;
        int ra = okA ? (row0 + r) : 0;
        uint32_t sa = (uint32_t)__cvta_generic_to_shared(sA + r * ROWB + q * 16);
        cp_async16(sa, A + (size_t)ra * K + k0 + q * 8, okA);
        uint32_t sb = (uint32_t)__cvta_generic_to_shared(sB + r * ROWB + q * 16);
        cp_async16(sb, W + (size_t)(col0 + r) * K + k0 + q * 8, true);
    }
    cp_commit();
}

template<int NPAIRS, bool SPLITN, bool RELU, bool CBF16>
__global__ __launch_bounds__(256, 2)
void gemm_bf16_kernel(const __nv_bfloat16* __restrict__ A0, const __nv_bfloat16* __restrict__ W0,
                      const __nv_bfloat16* __restrict__ A1, const __nv_bfloat16* __restrict__ W1,
                      void* __restrict__ C0v, void* __restrict__ C1v,
                      const float* __restrict__ bias,
                      int M, int N, int K) {
    __shared__ __align__(16) char sAm[2 * STAGE];
    __shared__ __align__(16) char sBm[2 * STAGE];

    const int tid = threadIdx.x;
    const int bx = blockIdx.x, by = blockIdx.y;

    const __nv_bfloat16* A = A0;
    const __nv_bfloat16* W = W0;
    void* Cv = C0v;
    bool useBias = (bias != nullptr);
    int col0;
    if (SPLITN) {
        int nHalf = N / BN;
        bool sel = bx >= nHalf;
        col0 = (sel ? bx - nHalf : bx) * BN;
        if (sel) { W = W1; Cv = C1v; useBias = false; }
    } else {
        col0 = bx * BN;
    }
    const int row0 = by * BM;

    const int w  = tid >> 5, lane = tid & 31;
    const int wr = w >> 2;          // 0..1 -> m offset wr*64
    const int wc = w & 3;           // 0..3 -> n offset wc*32
    const int g  = lane >> 2;       // 0..7
    const int tg = lane & 3;        // 0..3

    // ldmatrix lane address components
    const uint32_t aLane = (uint32_t)((lane & 15) * ROWB + (lane >> 4) * 16);
    const uint32_t bLane = (uint32_t)((((lane >> 4) * 8) + (lane & 7)) * ROWB + ((lane >> 3) & 1) * 16);
    const uint32_t sAu = (uint32_t)__cvta_generic_to_shared(sAm);
    const uint32_t sBu = (uint32_t)__cvta_generic_to_shared(sBm);

    float acc[4][4][4];
#pragma unroll
    for (int mi = 0; mi < 4; mi++)
#pragma unroll
        for (int ni = 0; ni < 4; ni++)
#pragma unroll
            for (int q = 0; q < 4; q++) acc[mi][ni][q] = 0.f;

    const int stepsPerK = K / BK;
    const int nT = stepsPerK * NPAIRS;

    auto src_of = [&](int s, const __nv_bfloat16*& Ap, const __nv_bfloat16*& Wp, int& k0) {
        if (NPAIRS == 2 && s >= stepsPerK) { Ap = A1; Wp = W1; k0 = (s - stepsPerK) * BK; }
        else { Ap = A; Wp = W; k0 = s * BK; }
    };

    {
        const __nv_bfloat16 *Ap, *Wp; int k0;
        src_of(0, Ap, Wp, k0);
        load_tile(sAm, sBm, Ap, Wp, M, K, row0, col0, k0, tid);
    }

    for (int t = 0; t < nT; t++) {
        const int buf = t & 1;
        if (t + 1 < nT) {
            const __nv_bfloat16 *Ap, *Wp; int k0;
            src_of(t + 1, Ap, Wp, k0);
            load_tile(sAm + ((t + 1) & 1) * STAGE, sBm + ((t + 1) & 1) * STAGE,
                      Ap, Wp, M, K, row0, col0, k0, tid);
            cp_wait<1>();
        } else {
            cp_wait<0>();
        }
        __syncthreads();

        const uint32_t aBase = sAu + buf * STAGE;
        const uint32_t bBase = sBu + buf * STAGE;
#pragma unroll
        for (int half = 0; half < 2; half++) {   // k = half*16 within BK=32
            const uint32_t ks2 = half * 32;      // bytes
            uint32_t a[4][4], b[2][4];
#pragma unroll
            for (int mi = 0; mi < 4; mi++)
                ldsm_x4(a[mi], aBase + (uint32_t)((wr * 64 + mi * 16) * ROWB) + aLane + ks2);
#pragma unroll
            for (int n2 = 0; n2 < 2; n2++)
                ldsm_x4(b[n2], bBase + (uint32_t)((wc * 32 + n2 * 16) * ROWB) + bLane + ks2);
#pragma unroll
            for (int mi = 0; mi < 4; mi++)
#pragma unroll
                for (int ni = 0; ni < 4; ni++)
                    mma_bf16(acc[mi][ni], a[mi][0], a[mi][1], a[mi][2], a[mi][3],
                             b[ni >> 1][(ni & 1) * 2], b[ni >> 1][(ni & 1) * 2 + 1]);
        }
        __syncthreads();
    }

    // epilogue
#pragma unroll
    for (int mi = 0; mi < 4; mi++) {
        int rbase = row0 + wr * 64 + mi * 16 + g;
#pragma unroll
        for (int half = 0; half < 2; half++) {
            int r = rbase + half * 8;
            if (r < M) {
#pragma unroll
                for (int ni = 0; ni < 4; ni++) {
                    int c = col0 + wc * 32 + ni * 8 + 2 * tg;
                    float v0 = acc[mi][ni][half * 2 + 0];
                    float v1 = acc[mi][ni][half * 2 + 1];
                    if (useBias) { v0 += bias[c]; v1 += bias[c + 1]; }
                    if (RELU) { v0 = fmaxf(v0, 0.f); v1 = fmaxf(v1, 0.f); }
                    if (CBF16) {
                        __nv_bfloat16* crow = (__nv_bfloat16*)Cv + (size_t)r * N;
                        *(__nv_bfloat162*)(crow + c) = __floats2bfloat162_rn(v0, v1);
                    } else {
                        float* crow = (float*)Cv + (size_t)r * N;
                        *(float2*)(crow + c) = make_float2(v0, v1);
                    }
                }
            }
        }
    }
}

// ---------------------------------------------------------------------------
// Utility kernels
// ---------------------------------------------------------------------------
__global__ void zero_kernel(float* __restrict__ p, size_t n4) {
    size_t i = (size_t)blockIdx.x * blockDim.x + threadIdx.x;
    size_t stride = (size_t)gridDim.x * blockDim.x;
    float4 z = make_float4(0.f, 0.f, 0.f, 0.f);
    float4* p4 = (float4*)p;
    for (; i < n4; i += stride) p4[i] = z;
}

__global__ void cvt_bf16_kernel(const float* __restrict__ s,
                                __nv_bfloat16* __restrict__ d, size_t n4) {
    size_t i = (size_t)blockIdx.x * blockDim.x + threadIdx.x;
    size_t stride = (size_t)gridDim.x * blockDim.x;
    const float4* s4 = (const float4*)s;
    __nv_bfloat162* d2 = (__nv_bfloat162*)d;
    for (; i < n4; i += stride) {
        float4 v = s4[i];
        d2[2 * i + 0] = __floats2bfloat162_rn(v.x, v.y);
        d2[2 * i + 1] = __floats2bfloat162_rn(v.z, v.w);
    }
}

__global__ void count_kernel(const int* __restrict__ dst, float* __restrict__ cnt) {
    int e = blockIdx.x * blockDim.x + threadIdx.x;
    if (e < N_EDGES) atomicAdd(&cnt[dst[e]], 1.0f);
}

__global__ void scatter_kernel(const float* __restrict__ X,
                               const int* __restrict__ src,
                               const int* __restrict__ dst,
                               float* __restrict__ agg, int D4) {
    int e = blockIdx.x;
    int s = src[e], d = dst[e];
    const float4* xs = (const float4*)(X + (size_t)s * D4 * 4);
    float* ag = agg + (size_t)d * D4 * 4;
    for (int i = threadIdx.x; i < D4; i += blockDim.x) {
        float4 v = xs[i];
        atomicAdd(ag + 4 * i + 0, v.x);
        atomicAdd(ag + 4 * i + 1, v.y);
        atomicAdd(ag + 4 * i + 2, v.z);
        atomicAdd(ag + 4 * i + 3, v.w);
    }
}

// mean (fp32) -> bf16 output for the GEMM
__global__ void mean_bf16_kernel(const float* __restrict__ agg,
                                 const float* __restrict__ cnt,
                                 __nv_bfloat16* __restrict__ out, int D4) {
    int n = blockIdx.x;
    float inv = 1.0f / fmaxf(cnt[n], 1.0f);
    const float4* p = (const float4*)(agg + (size_t)n * D4 * 4);
    __nv_bfloat162* o2 = (__nv_bfloat162*)(out + (size_t)n * D4 * 4);
    for (int i = threadIdx.x; i < D4; i += blockDim.x) {
        float4 v = p[i];
        o2[2 * i + 0] = __floats2bfloat162_rn(v.x * inv, v.y * inv);
        o2[2 * i + 1] = __floats2bfloat162_rn(v.z * inv, v.w * inv);
    }
}

__global__ void final_kernel(float* __restrict__ out,
                             const float* __restrict__ aggo,
                             const float* __restrict__ cnt) {
    __shared__ float red[256];
    const int n = blockIdx.x;
    const int t = threadIdx.x;
    float inv = 1.0f / fmaxf(cnt[n], 1.0f);
    size_t idx = (size_t)n * OUT_DIM + t;
    float v = out[idx] + aggo[idx] * inv;

    red[t] = v;
    __syncthreads();
    for (int s = 128; s > 0; s >>= 1) {
        if (t < s) red[t] = fmaxf(red[t], red[t + s]);
        __syncthreads();
    }
    float m = red[0];
    __syncthreads();

    red[t] = expf(v - m);
    __syncthreads();
    for (int s = 128; s > 0; s >>= 1) {
        if (t < s) red[t] += red[t + s];
        __syncthreads();
    }
    float lse = logf(red[0]);
    out[idx] = v - m - lse;
}

// ---------------------------------------------------------------------------
// Launch
// ---------------------------------------------------------------------------
extern "C" void kernel_launch(void* const* d_in, const int* in_sizes, int n_in,
                              void* d_out, int out_size) {
    const float* x   = (const float*)d_in[0];
    const int*   ei  = (const int*)  d_in[1];
    const float* W1l = (const float*)d_in[2];
    const float* b1l = (const float*)d_in[3];
    const float* W1r = (const float*)d_in[4];
    const float* W2l = (const float*)d_in[5];
    const float* b2l = (const float*)d_in[6];
    const float* W2r = (const float*)d_in[7];
    float* out = (float*)d_out;

    const int* src = ei;
    const int* dst = ei + N_EDGES;

    float *agg1, *t2, *aggo, *cnt;
    __nv_bfloat16 *agg1b, *xb, *h, *w1lb, *w1rb, *w2lb, *w2rb;
    cudaGetSymbolAddress((void**)&agg1,  g_agg1);
    cudaGetSymbolAddress((void**)&agg1b, g_agg1b);
    cudaGetSymbolAddress((void**)&xb,    g_xb);
    cudaGetSymbolAddress((void**)&h,     g_h);
    cudaGetSymbolAddress((void**)&t2,    g_t2);
    cudaGetSymbolAddress((void**)&aggo,  g_aggo);
    cudaGetSymbolAddress((void**)&cnt,   g_cnt);
    cudaGetSymbolAddress((void**)&w1lb,  g_w1lb);
    cudaGetSymbolAddress((void**)&w1rb,  g_w1rb);
    cudaGetSymbolAddress((void**)&w2lb,  g_w2lb);
    cudaGetSymbolAddress((void**)&w2rb,  g_w2rb);

    // ---- counts + layer-1 aggregation (fp32 atomics) ----
    zero_kernel<<<2048, 256>>>(agg1, (size_t)N_NODES * IN_DIM / 4);
    zero_kernel<<<512, 256>>>(aggo, (size_t)N_NODES * OUT_DIM / 4);
    zero_kernel<<<16, 256>>>(cnt, N_NODES / 4);
    count_kernel<<<(N_EDGES + 255) / 256, 256>>>(dst, cnt);
    scatter_kernel<<<N_EDGES, 256>>>(x, src, dst, agg1, IN_DIM / 4);
    mean_bf16_kernel<<<N_NODES, 256>>>(agg1, cnt, agg1b, IN_DIM / 4);

    // ---- bf16 conversion of MMA operands ----
    cvt_bf16_kernel<<<2048, 256>>>(x,   xb,   (size_t)N_NODES * IN_DIM / 4);
    cvt_bf16_kernel<<<1024, 256>>>(W1l, w1lb, (size_t)HID * IN_DIM / 4);
    cvt_bf16_kernel<<<1024, 256>>>(W1r, w1rb, (size_t)HID * IN_DIM / 4);
    cvt_bf16_kernel<<<256, 256>>>(W2l, w2lb, (size_t)OUT_DIM * HID / 4);
    cvt_bf16_kernel<<<256, 256>>>(W2r, w2rb, (size_t)OUT_DIM * HID / 4);

    // ---- layer 1: h(bf16) = relu(mean1@W1l^T + x@W1r^T + b1) ----
    {
        dim3 grid(HID / BN, (N_NODES + BM - 1) / BM);
        gemm_bf16_kernel<2, false, true, true><<<grid, 256>>>(
            agg1b, w1lb, xb, w1rb, h, nullptr, b1l, N_NODES, HID, IN_DIM);
    }

    // ---- layer 2: out = h@W2r^T + b2 ; t2 = h@W2l^T (split-N) ----
    {
        dim3 grid(2 * OUT_DIM / BN, (N_NODES + BM - 1) / BM);
        gemm_bf16_kernel<1, true, false, false><<<grid, 256>>>(
            h, w2rb, nullptr, w2lb, out, t2, b2l, N_NODES, OUT_DIM, HID);
    }

    // ---- scatter-mean of t2 in 256-dim space ----
    scatter_kernel<<<N_EDGES, 64>>>(t2, src, dst, aggo, OUT_DIM / 4);

    // ---- out = log_softmax(out + aggo/cnt) ----
    final_kernel<<<N_NODES, 256>>>(out, aggo, cnt);
}

// round 6
// speedup vs baseline: 2.2406x; 1.2164x over previous
#include <cuda_runtime.h>
#include <cuda_bf16.h>
#include <math.h>
#include <stdint.h>

#define N_NODES 10000
#define N_EDGES 80000
#define IN_DIM  1024
#define HID     4096
#define OUT_DIM 256

// ---------------------------------------------------------------------------
// Scratch (device globals)
// ---------------------------------------------------------------------------
__device__ __align__(16) __nv_bfloat16 g_agg1b[(size_t)N_NODES * IN_DIM];   // 20 MB
__device__ __align__(16) __nv_bfloat16 g_xb[(size_t)N_NODES * IN_DIM];      // 20 MB
__device__ __align__(16) __nv_bfloat16 g_h[(size_t)N_NODES * HID];          // 80 MB
__device__ __align__(16) float g_t2[(size_t)N_NODES * OUT_DIM];             // 10 MB
__device__ __align__(16) __nv_bfloat16 g_w1lb[(size_t)HID * IN_DIM];        // 8 MB
__device__ __align__(16) __nv_bfloat16 g_w1rb[(size_t)HID * IN_DIM];        // 8 MB
__device__ __align__(16) __nv_bfloat16 g_w2lb[(size_t)OUT_DIM * HID];       // 2 MB
__device__ __align__(16) __nv_bfloat16 g_w2rb[(size_t)OUT_DIM * HID];       // 2 MB
// CSR
__device__ int g_deg[N_NODES];
__device__ int g_rowptr[N_NODES + 1];
__device__ int g_pos[N_NODES];
__device__ int g_csrc[N_EDGES];

// ---------------------------------------------------------------------------
// MMA / async-copy helpers
// ---------------------------------------------------------------------------
__device__ __forceinline__ void mma_bf16(float c[4],
        uint32_t a0, uint32_t a1, uint32_t a2, uint32_t a3,
        uint32_t b0, uint32_t b1) {
    asm volatile(
        "mma.sync.aligned.m16n8k16.row.col.f32.bf16.bf16.f32 "
        "{%0,%1,%2,%3},{%4,%5,%6,%7},{%8,%9},{%0,%1,%2,%3};"
        : "+f"(c[0]), "+f"(c[1]), "+f"(c[2]), "+f"(c[3])
        : "r"(a0), "r"(a1), "r"(a2), "r"(a3), "r"(b0), "r"(b1));
}
__device__ __forceinline__ void ldsm_x4(uint32_t r[4], uint32_t addr) {
    asm volatile("ldmatrix.sync.aligned.m8n8.x4.shared.b16 {%0,%1,%2,%3}, [%4];"
                 : "=r"(r[0]), "=r"(r[1]), "=r"(r[2]), "=r"(r[3]) : "r"(addr));
}
__device__ __forceinline__ void cp_async16(uint32_t smem, const void* g, bool valid) {
    int sz = valid ? 16 : 0;
    asm volatile("cp.async.ca.shared.global [%0], [%1], 16, %2;\n"
                 :: "r"(smem), "l"(g), "r"(sz));
}
__device__ __forceinline__ void cp_commit() { asm volatile("cp.async.commit_group;\n"); }
template<int W> __device__ __forceinline__ void cp_wait() {
    asm volatile("cp.async.wait_group %0;\n" :: "n"(W));
}

// ---------------------------------------------------------------------------
// BF16 tensor-core GEMM (unchanged from R5):  C[M,N] = A[M,K] @ W[N,K]^T
// ---------------------------------------------------------------------------
#define BM 128
#define BN 128
#define BK 32
#define ROWB 80
#define STAGE (128 * ROWB)

__device__ __forceinline__ void load_tile(char* sA, char* sB,
        const __nv_bfloat16* __restrict__ A, const __nv_bfloat16* __restrict__ W,
        int M, int K, int row0, int col0, int k0, int tid) {
#pragma unroll
    for (int it = 0; it < 2; it++) {
        int c = tid + it * 256;
        int r = c >> 2, q = c & 3;
        bool okA = (row0 + r) < M;
        int ra = okA ? (row0 + r) : 0;
        uint32_t sa = (uint32_t)__cvta_generic_to_shared(sA + r * ROWB + q * 16);
        cp_async16(sa, A + (size_t)ra * K + k0 + q * 8, okA);
        uint32_t sb = (uint32_t)__cvta_generic_to_shared(sB + r * ROWB + q * 16);
        cp_async16(sb, W + (size_t)(col0 + r) * K + k0 + q * 8, true);
    }
    cp_commit();
}

template<int NPAIRS, bool SPLITN, bool RELU, bool CBF16>
__global__ __launch_bounds__(256, 2)
void gemm_bf16_kernel(const __nv_bfloat16* __restrict__ A0, const __nv_bfloat16* __restrict__ W0,
                      const __nv_bfloat16* __restrict__ A1, const __nv_bfloat16* __restrict__ W1,
                      void* __restrict__ C0v, void* __restrict__ C1v,
                      const float* __restrict__ bias,
                      int M, int N, int K) {
    __shared__ __align__(16) char sAm[2 * STAGE];
    __shared__ __align__(16) char sBm[2 * STAGE];

    const int tid = threadIdx.x;
    const int bx = blockIdx.x, by = blockIdx.y;

    const __nv_bfloat16* A = A0;
    const __nv_bfloat16* W = W0;
    void* Cv = C0v;
    bool useBias = (bias != nullptr);
    int col0;
    if (SPLITN) {
        int nHalf = N / BN;
        bool sel = bx >= nHalf;
        col0 = (sel ? bx - nHalf : bx) * BN;
        if (sel) { W = W1; Cv = C1v; useBias = false; }
    } else {
        col0 = bx * BN;
    }
    const int row0 = by * BM;

    const int w  = tid >> 5, lane = tid & 31;
    const int wr = w >> 2;
    const int wc = w & 3;
    const int g  = lane >> 2;
    const int tg = lane & 3;

    const uint32_t aLane = (uint32_t)((lane & 15) * ROWB + (lane >> 4) * 16);
    const uint32_t bLane = (uint32_t)((((lane >> 4) * 8) + (lane & 7)) * ROWB + ((lane >> 3) & 1) * 16);
    const uint32_t sAu = (uint32_t)__cvta_generic_to_shared(sAm);
    const uint32_t sBu = (uint32_t)__cvta_generic_to_shared(sBm);

    float acc[4][4][4];
#pragma unroll
    for (int mi = 0; mi < 4; mi++)
#pragma unroll
        for (int ni = 0; ni < 4; ni++)
#pragma unroll
            for (int q = 0; q < 4; q++) acc[mi][ni][q] = 0.f;

    const int stepsPerK = K / BK;
    const int nT = stepsPerK * NPAIRS;

    auto src_of = [&](int s, const __nv_bfloat16*& Ap, const __nv_bfloat16*& Wp, int& k0) {
        if (NPAIRS == 2 && s >= stepsPerK) { Ap = A1; Wp = W1; k0 = (s - stepsPerK) * BK; }
        else { Ap = A; Wp = W; k0 = s * BK; }
    };

    {
        const __nv_bfloat16 *Ap, *Wp; int k0;
        src_of(0, Ap, Wp, k0);
        load_tile(sAm, sBm, Ap, Wp, M, K, row0, col0, k0, tid);
    }

    for (int t = 0; t < nT; t++) {
        const int buf = t & 1;
        if (t + 1 < nT) {
            const __nv_bfloat16 *Ap, *Wp; int k0;
            src_of(t + 1, Ap, Wp, k0);
            load_tile(sAm + ((t + 1) & 1) * STAGE, sBm + ((t + 1) & 1) * STAGE,
                      Ap, Wp, M, K, row0, col0, k0, tid);
            cp_wait<1>();
        } else {
            cp_wait<0>();
        }
        __syncthreads();

        const uint32_t aBase = sAu + buf * STAGE;
        const uint32_t bBase = sBu + buf * STAGE;
#pragma unroll
        for (int half = 0; half < 2; half++) {
            const uint32_t ks2 = half * 32;
            uint32_t a[4][4], b[2][4];
#pragma unroll
            for (int mi = 0; mi < 4; mi++)
                ldsm_x4(a[mi], aBase + (uint32_t)((wr * 64 + mi * 16) * ROWB) + aLane + ks2);
#pragma unroll
            for (int n2 = 0; n2 < 2; n2++)
                ldsm_x4(b[n2], bBase + (uint32_t)((wc * 32 + n2 * 16) * ROWB) + bLane + ks2);
#pragma unroll
            for (int mi = 0; mi < 4; mi++)
#pragma unroll
                for (int ni = 0; ni < 4; ni++)
                    mma_bf16(acc[mi][ni], a[mi][0], a[mi][1], a[mi][2], a[mi][3],
                             b[ni >> 1][(ni & 1) * 2], b[ni >> 1][(ni & 1) * 2 + 1]);
        }
        __syncthreads();
    }

#pragma unroll
    for (int mi = 0; mi < 4; mi++) {
        int rbase = row0 + wr * 64 + mi * 16 + g;
#pragma unroll
        for (int half = 0; half < 2; half++) {
            int r = rbase + half * 8;
            if (r < M) {
#pragma unroll
                for (int ni = 0; ni < 4; ni++) {
                    int c = col0 + wc * 32 + ni * 8 + 2 * tg;
                    float v0 = acc[mi][ni][half * 2 + 0];
                    float v1 = acc[mi][ni][half * 2 + 1];
                    if (useBias) { v0 += bias[c]; v1 += bias[c + 1]; }
                    if (RELU) { v0 = fmaxf(v0, 0.f); v1 = fmaxf(v1, 0.f); }
                    if (CBF16) {
                        __nv_bfloat16* crow = (__nv_bfloat16*)Cv + (size_t)r * N;
                        *(__nv_bfloat162*)(crow + c) = __floats2bfloat162_rn(v0, v1);
                    } else {
                        float* crow = (float*)Cv + (size_t)r * N;
                        *(float2*)(crow + c) = make_float2(v0, v1);
                    }
                }
            }
        }
    }
}

// ---------------------------------------------------------------------------
// CSR construction
// ---------------------------------------------------------------------------
__global__ void zero_int_kernel(int* __restrict__ p, int n) {
    int i = blockIdx.x * blockDim.x + threadIdx.x;
    if (i < n) p[i] = 0;
}
__global__ void deg_kernel(const int* __restrict__ dst, int* __restrict__ deg) {
    int e = blockIdx.x * blockDim.x + threadIdx.x;
    if (e < N_EDGES) atomicAdd(&deg[dst[e]], 1);
}
// single block, 1024 threads: exclusive scan of deg -> rowptr (and pos copy)
__global__ void scan_kernel(const int* __restrict__ deg, int* __restrict__ rowptr,
                            int* __restrict__ pos) {
    __shared__ int part[1024];
    const int CH = 10;                  // 1024*10 >= 10000
    int t = threadIdx.x;
    int base = t * CH;
    int local[CH];
    int s = 0;
#pragma unroll
    for (int i = 0; i < CH; i++) {
        int idx = base + i;
        int d = (idx < N_NODES) ? deg[idx] : 0;
        local[i] = s;
        s += d;
    }
    part[t] = s;
    __syncthreads();
    for (int off = 1; off < 1024; off <<= 1) {
        int v = part[t];
        int u = (t >= off) ? part[t - off] : 0;
        __syncthreads();
        part[t] = v + u;
        __syncthreads();
    }
    int pre = (t == 0) ? 0 : part[t - 1];
#pragma unroll
    for (int i = 0; i < CH; i++) {
        int idx = base + i;
        if (idx < N_NODES) { rowptr[idx] = pre + local[i]; pos[idx] = pre + local[i]; }
    }
    if (t == 1023) rowptr[N_NODES] = part[1023];
}
__global__ void fill_csr_kernel(const int* __restrict__ src, const int* __restrict__ dst,
                                int* __restrict__ pos, int* __restrict__ csrc) {
    int e = blockIdx.x * blockDim.x + threadIdx.x;
    if (e < N_EDGES) {
        int slot = atomicAdd(&pos[dst[e]], 1);
        csrc[slot] = src[e];
    }
}

// ---------------------------------------------------------------------------
// Gather-mean (layer 1): block per node, 256 threads x 4 features = 1024
// reads bf16 x, accumulates fp32, writes bf16 mean.
// ---------------------------------------------------------------------------
__global__ void gather1_kernel(const __nv_bfloat16* __restrict__ xb,
                               const int* __restrict__ rowptr,
                               const int* __restrict__ csrc,
                               __nv_bfloat16* __restrict__ aggb) {
    const int n = blockIdx.x;
    const int t = threadIdx.x;
    const int beg = rowptr[n], end = rowptr[n + 1];
    float a0 = 0.f, a1 = 0.f, a2 = 0.f, a3 = 0.f;
    int j = beg;
    for (; j + 1 < end; j += 2) {
        int s0 = csrc[j], s1 = csrc[j + 1];
        uint2 u0 = *(const uint2*)(xb + (size_t)s0 * IN_DIM + t * 4);
        uint2 u1 = *(const uint2*)(xb + (size_t)s1 * IN_DIM + t * 4);
        __nv_bfloat162 p0 = *(__nv_bfloat162*)&u0.x, p1 = *(__nv_bfloat162*)&u0.y;
        __nv_bfloat162 q0 = *(__nv_bfloat162*)&u1.x, q1 = *(__nv_bfloat162*)&u1.y;
        a0 += __bfloat162float(p0.x) + __bfloat162float(q0.x);
        a1 += __bfloat162float(p0.y) + __bfloat162float(q0.y);
        a2 += __bfloat162float(p1.x) + __bfloat162float(q1.x);
        a3 += __bfloat162float(p1.y) + __bfloat162float(q1.y);
    }
    if (j < end) {
        int s0 = csrc[j];
        uint2 u0 = *(const uint2*)(xb + (size_t)s0 * IN_DIM + t * 4);
        __nv_bfloat162 p0 = *(__nv_bfloat162*)&u0.x, p1 = *(__nv_bfloat162*)&u0.y;
        a0 += __bfloat162float(p0.x);
        a1 += __bfloat162float(p0.y);
        a2 += __bfloat162float(p1.x);
        a3 += __bfloat162float(p1.y);
    }
    float inv = 1.0f / fmaxf((float)(end - beg), 1.0f);
    __nv_bfloat162* o = (__nv_bfloat162*)(aggb + (size_t)n * IN_DIM + t * 4);
    o[0] = __floats2bfloat162_rn(a0 * inv, a1 * inv);
    o[1] = __floats2bfloat162_rn(a2 * inv, a3 * inv);
}

// ---------------------------------------------------------------------------
// Conversions
// ---------------------------------------------------------------------------
__global__ void cvt_bf16_kernel(const float* __restrict__ s,
                                __nv_bfloat16* __restrict__ d, size_t n4) {
    size_t i = (size_t)blockIdx.x * blockDim.x + threadIdx.x;
    size_t stride = (size_t)gridDim.x * blockDim.x;
    const float4* s4 = (const float4*)s;
    __nv_bfloat162* d2 = (__nv_bfloat162*)d;
    for (; i < n4; i += stride) {
        float4 v = s4[i];
        d2[2 * i + 0] = __floats2bfloat162_rn(v.x, v.y);
        d2[2 * i + 1] = __floats2bfloat162_rn(v.z, v.w);
    }
}

// ---------------------------------------------------------------------------
// Final fused: gather-mean of t2 + add + log_softmax. Block per node, 256 thr.
// ---------------------------------------------------------------------------
__global__ void final_kernel(float* __restrict__ out,
                             const float* __restrict__ t2,
                             const int* __restrict__ rowptr,
                             const int* __restrict__ csrc) {
    __shared__ float red[256];
    const int n = blockIdx.x;
    const int t = threadIdx.x;
    const int beg = rowptr[n], end = rowptr[n + 1];

    float acc = 0.f;
    int j = beg;
    for (; j + 1 < end; j += 2) {
        int s0 = csrc[j], s1 = csrc[j + 1];
        acc += t2[(size_t)s0 * OUT_DIM + t] + t2[(size_t)s1 * OUT_DIM + t];
    }
    if (j < end) acc += t2[(size_t)csrc[j] * OUT_DIM + t];

    float inv = 1.0f / fmaxf((float)(end - beg), 1.0f);
    size_t idx = (size_t)n * OUT_DIM + t;
    float v = out[idx] + acc * inv;

    red[t] = v;
    __syncthreads();
    for (int s = 128; s > 0; s >>= 1) {
        if (t < s) red[t] = fmaxf(red[t], red[t + s]);
        __syncthreads();
    }
    float m = red[0];
    __syncthreads();

    red[t] = expf(v - m);
    __syncthreads();
    for (int s = 128; s > 0; s >>= 1) {
        if (t < s) red[t] += red[t + s];
        __syncthreads();
    }
    float lse = logf(red[0]);
    out[idx] = v - m - lse;
}

// ---------------------------------------------------------------------------
// Launch
// ---------------------------------------------------------------------------
extern "C" void kernel_launch(void* const* d_in, const int* in_sizes, int n_in,
                              void* d_out, int out_size) {
    const float* x   = (const float*)d_in[0];
    const int*   ei  = (const int*)  d_in[1];
    const float* W1l = (const float*)d_in[2];
    const float* b1l = (const float*)d_in[3];
    const float* W1r = (const float*)d_in[4];
    const float* W2l = (const float*)d_in[5];
    const float* b2l = (const float*)d_in[6];
    const float* W2r = (const float*)d_in[7];
    float* out = (float*)d_out;

    const int* src = ei;
    const int* dst = ei + N_EDGES;

    float* t2;
    __nv_bfloat16 *agg1b, *xb, *h, *w1lb, *w1rb, *w2lb, *w2rb;
    int *deg, *rowptr, *pos, *csrc;
    cudaGetSymbolAddress((void**)&agg1b, g_agg1b);
    cudaGetSymbolAddress((void**)&xb,    g_xb);
    cudaGetSymbolAddress((void**)&h,     g_h);
    cudaGetSymbolAddress((void**)&t2,    g_t2);
    cudaGetSymbolAddress((void**)&w1lb,  g_w1lb);
    cudaGetSymbolAddress((void**)&w1rb,  g_w1rb);
    cudaGetSymbolAddress((void**)&w2lb,  g_w2lb);
    cudaGetSymbolAddress((void**)&w2rb,  g_w2rb);
    cudaGetSymbolAddress((void**)&deg,    g_deg);
    cudaGetSymbolAddress((void**)&rowptr, g_rowptr);
    cudaGetSymbolAddress((void**)&pos,    g_pos);
    cudaGetSymbolAddress((void**)&csrc,   g_csrc);

    // ---- CSR build ----
    zero_int_kernel<<<(N_NODES + 255) / 256, 256>>>(deg, N_NODES);
    deg_kernel<<<(N_EDGES + 255) / 256, 256>>>(dst, deg);
    scan_kernel<<<1, 1024>>>(deg, rowptr, pos);
    fill_csr_kernel<<<(N_EDGES + 255) / 256, 256>>>(src, dst, pos, csrc);

    // ---- bf16 conversions ----
    cvt_bf16_kernel<<<2048, 256>>>(x,   xb,   (size_t)N_NODES * IN_DIM / 4);
    cvt_bf16_kernel<<<1024, 256>>>(W1l, w1lb, (size_t)HID * IN_DIM / 4);
    cvt_bf16_kernel<<<1024, 256>>>(W1r, w1rb, (size_t)HID * IN_DIM / 4);
    cvt_bf16_kernel<<<256, 256>>>(W2l, w2lb, (size_t)OUT_DIM * HID / 4);
    cvt_bf16_kernel<<<256, 256>>>(W2r, w2rb, (size_t)OUT_DIM * HID / 4);

    // ---- layer-1 aggregation: gather-mean in bf16 ----
    gather1_kernel<<<N_NODES, 256>>>(xb, rowptr, csrc, agg1b);

    // ---- layer 1: h(bf16) = relu(mean1@W1l^T + x@W1r^T + b1) ----
    {
        dim3 grid(HID / BN, (N_NODES + BM - 1) / BM);
        gemm_bf16_kernel<2, false, true, true><<<grid, 256>>>(
            agg1b, w1lb, xb, w1rb, h, nullptr, b1l, N_NODES, HID, IN_DIM);
    }

    // ---- layer 2: out = h@W2r^T + b2 ; t2 = h@W2l^T (split-N, one launch) ----
    {
        dim3 grid(2 * OUT_DIM / BN, (N_NODES + BM - 1) / BM);
        gemm_bf16_kernel<1, true, false, false><<<grid, 256>>>(
            h, w2rb, nullptr, w2lb, out, t2, b2l, N_NODES, OUT_DIM, HID);
    }

    // ---- fused: out = log_softmax(out + mean_gather(t2)) ----
    final_kernel<<<N_NODES, 256>>>(out, t2, rowptr, csrc);
}